// round 2
// baseline (speedup 1.0000x reference)
#include <cuda_runtime.h>

// Problem constants
static constexpr int B_ = 4;
static constexpr int T_ = 1024;
static constexpr int C_ = 768;
static constexpr int H_ = 12;
static constexpr int D_ = 64;
static constexpr int C3 = 3 * C_;          // 2304

// Scratch (device globals; no allocations allowed)
__device__ float g_qkv[(size_t)B_ * T_ * C3];            // [B,T,3,H,D] packed as [B*T, 2304]
__device__ float g_logits[(size_t)B_ * H_ * T_ * T_];    // [B,H,T,T]
__device__ float g_y[(size_t)B_ * T_ * C_];              // [B,T,C] attention output pre-proj

// ---------------------------------------------------------------------------
// Generic batched tiled SGEMM: C = scale * A * op(B) (+ biasVec)(+ biasMat)(+ maskMat)
//   A: M x K row-major (lda), op(B): K x N.  TRANSB=false: B is KxN (ldb).
//   TRANSB=true: B is NxK row-major (ldb) and we compute A * B^T.
//   Batched over grid.z = bb*Hdim + hh with independent strides for b and h.
// Tile: 64x64, K-tile 16, 256 threads, 4x4 per-thread microtile.
// All dims assumed divisible (64 for M/N, 16 for K) -- true for this problem.
// ---------------------------------------------------------------------------
template <bool TRANSB>
__global__ __launch_bounds__(256) void gemm_kernel(
    const float* __restrict__ A, const float* __restrict__ Bm, float* __restrict__ Cm,
    const float* __restrict__ biasVec, const float* __restrict__ biasMat,
    const float* __restrict__ maskMat, float scale,
    int M, int N, int K, int lda, int ldb, int ldc,
    int Hdim,
    long sAb, long sAh, long sBb, long sBh, long sCb, long sCh,
    long sBMb, long sBMh, long sMb, int ldE)
{
    const int bz = blockIdx.z;
    const int bb = bz / Hdim;
    const int hh = bz - bb * Hdim;
    A  += bb * sAb + hh * sAh;
    Bm += bb * sBb + hh * sBh;
    Cm += bb * sCb + hh * sCh;
    if (biasMat) biasMat += bb * sBMb + hh * sBMh;
    if (maskMat) maskMat += bb * sMb;

    __shared__ float As[16][68];
    __shared__ float Bs[16][68];

    const int tid = threadIdx.x;
    const int m0 = blockIdx.y * 64;
    const int n0 = blockIdx.x * 64;

    const int tx = tid & 15;         // 0..15 -> n microtile
    const int ty = tid >> 4;         // 0..15 -> m microtile

    // loader indices
    const int la_m = tid >> 2;            // 0..63 (row of A tile, or row-n of B tile if TRANSB)
    const int la_k = (tid & 3) * 4;       // 0,4,8,12
    const int lb_k = tid >> 4;            // 0..15 (NN B loader)
    const int lb_n = (tid & 15) * 4;      // 0..60

    float acc[4][4] = {};

    for (int k0 = 0; k0 < K; k0 += 16) {
        // Load A tile (64 x 16) transposed into As[k][m]
        {
            float4 av = *(const float4*)(A + (long)(m0 + la_m) * lda + (k0 + la_k));
            As[la_k + 0][la_m] = av.x;
            As[la_k + 1][la_m] = av.y;
            As[la_k + 2][la_m] = av.z;
            As[la_k + 3][la_m] = av.w;
        }
        if (TRANSB) {
            // B is N x K; tile rows are n, cols are k. Store Bs[k][n].
            float4 bv = *(const float4*)(Bm + (long)(n0 + la_m) * ldb + (k0 + la_k));
            Bs[la_k + 0][la_m] = bv.x;
            Bs[la_k + 1][la_m] = bv.y;
            Bs[la_k + 2][la_m] = bv.z;
            Bs[la_k + 3][la_m] = bv.w;
        } else {
            float4 bv = *(const float4*)(Bm + (long)(k0 + lb_k) * ldb + (n0 + lb_n));
            *(float4*)&Bs[lb_k][lb_n] = bv;
        }
        __syncthreads();

        #pragma unroll
        for (int kk = 0; kk < 16; kk++) {
            float4 a4 = *(const float4*)&As[kk][ty * 4];
            float4 b4 = *(const float4*)&Bs[kk][tx * 4];
            float a[4] = {a4.x, a4.y, a4.z, a4.w};
            float b[4] = {b4.x, b4.y, b4.z, b4.w};
            #pragma unroll
            for (int i = 0; i < 4; i++)
                #pragma unroll
                for (int j = 0; j < 4; j++)
                    acc[i][j] += a[i] * b[j];
        }
        __syncthreads();
    }

    // Epilogue
    #pragma unroll
    for (int i = 0; i < 4; i++) {
        const long m = m0 + ty * 4 + i;
        const long n = n0 + tx * 4;
        float4 r;
        r.x = acc[i][0] * scale;
        r.y = acc[i][1] * scale;
        r.z = acc[i][2] * scale;
        r.w = acc[i][3] * scale;
        if (biasVec) {
            float4 bv = *(const float4*)(biasVec + n);
            r.x += bv.x; r.y += bv.y; r.z += bv.z; r.w += bv.w;
        }
        if (biasMat) {
            float4 bm = *(const float4*)(biasMat + m * ldE + n);
            r.x += bm.x; r.y += bm.y; r.z += bm.z; r.w += bm.w;
        }
        if (maskMat) {
            float4 mk = *(const float4*)(maskMat + m * ldE + n);
            r.x += mk.x; r.y += mk.y; r.z += mk.z; r.w += mk.w;
        }
        *(float4*)(Cm + m * ldc + n) = r;
    }
}

// ---------------------------------------------------------------------------
// Row softmax over 1024-wide rows. One block (256 threads) per row; each
// thread owns exactly one float4.
// ---------------------------------------------------------------------------
__global__ __launch_bounds__(256) void softmax_kernel(const float* __restrict__ in,
                                                      float* __restrict__ out)
{
    const long row = blockIdx.x;
    const float4* ip = (const float4*)(in + row * 1024);
    float4* op = (float4*)(out + row * 1024);
    const int tid = threadIdx.x;
    __shared__ float sred[8];

    float4 v = ip[tid];
    float m = fmaxf(fmaxf(v.x, v.y), fmaxf(v.z, v.w));
    #pragma unroll
    for (int o = 16; o; o >>= 1) m = fmaxf(m, __shfl_xor_sync(0xffffffffu, m, o));
    if ((tid & 31) == 0) sred[tid >> 5] = m;
    __syncthreads();
    float gm = sred[0];
    #pragma unroll
    for (int i = 1; i < 8; i++) gm = fmaxf(gm, sred[i]);
    __syncthreads();

    v.x = __expf(v.x - gm);
    v.y = __expf(v.y - gm);
    v.z = __expf(v.z - gm);
    v.w = __expf(v.w - gm);
    float s = v.x + v.y + v.z + v.w;
    #pragma unroll
    for (int o = 16; o; o >>= 1) s += __shfl_xor_sync(0xffffffffu, s, o);
    if ((tid & 31) == 0) sred[tid >> 5] = s;
    __syncthreads();
    float gs = sred[0];
    #pragma unroll
    for (int i = 1; i < 8; i++) gs += sred[i];

    const float inv = 1.0f / gs;
    v.x *= inv; v.y *= inv; v.z *= inv; v.w *= inv;
    op[tid] = v;
}

// ---------------------------------------------------------------------------
// Launch: qkv GEMM -> QK^T(+scale+bias+mask) -> softmax -> AV -> proj
// ---------------------------------------------------------------------------
extern "C" void kernel_launch(void* const* d_in, const int* in_sizes, int n_in,
                              void* d_out, int out_size)
{
    const float* x     = (const float*)d_in[0];
    const float* mask  = (const float*)d_in[1];
    const float* bias  = (const float*)d_in[2];
    const float* Wqkv  = (const float*)d_in[3];
    const float* bqkv  = (const float*)d_in[4];
    const float* Wproj = (const float*)d_in[5];
    const float* bproj = (const float*)d_in[6];
    float* out = (float*)d_out;

    float *qkv, *logits, *y;
    cudaGetSymbolAddress((void**)&qkv,    g_qkv);
    cudaGetSymbolAddress((void**)&logits, g_logits);
    cudaGetSymbolAddress((void**)&y,      g_y);

    const long YN = (long)B_ * T_ * C_;
    const long AN = (long)B_ * H_ * T_ * T_;
    float* attn = ((long)out_size >= YN + AN) ? (out + YN) : logits;

    dim3 blk(256);

    // 1) qkv = x @ W_qkv + b_qkv        [4096 x 2304], K=768
    gemm_kernel<false><<<dim3(C3 / 64, (B_ * T_) / 64, 1), blk>>>(
        x, Wqkv, qkv, bqkv, nullptr, nullptr, 1.0f,
        B_ * T_, C3, C_, C_, C3, C3,
        1, 0, 0, 0, 0, 0, 0, 0, 0, 0, 0);

    // 2) logits = scale * q @ k^T + bias + mask   batched over (b,h)
    gemm_kernel<true><<<dim3(T_ / 64, T_ / 64, B_ * H_), blk>>>(
        qkv /*q base*/, qkv + C_ /*k base*/, logits,
        nullptr, bias, mask, 0.125f,
        T_, T_, D_, C3, C3, T_,
        H_,
        (long)T_ * C3, (long)D_,            // A (q) strides: b, h
        (long)T_ * C3, (long)D_,            // B (k) strides: b, h
        (long)H_ * T_ * T_, (long)T_ * T_,  // C (logits) strides: b, h
        (long)H_ * T_ * T_, (long)T_ * T_,  // biasMat strides: b, h
        (long)T_ * T_,                      // mask stride: b only
        T_);

    // 3) attn = softmax(logits) rows; written straight to d_out region if present
    softmax_kernel<<<B_ * H_ * T_, 256>>>(logits, attn);

    // 4) y[b,t,h*D+d] = attn @ v        batched over (b,h), N=64, K=1024
    gemm_kernel<false><<<dim3(1, T_ / 64, B_ * H_), blk>>>(
        attn, qkv + 2 * C_ /*v base*/, y, nullptr, nullptr, nullptr, 1.0f,
        T_, D_, T_, T_, C3, C_,
        H_,
        (long)H_ * T_ * T_, (long)T_ * T_,  // A (attn) strides: b, h
        (long)T_ * C3, (long)D_,            // B (v) strides: b, h
        (long)T_ * C_, (long)D_,            // C (y) strides: b, h
        0, 0, 0, 0);

    // 5) out = y @ W_proj + b_proj      [4096 x 768], K=768
    gemm_kernel<false><<<dim3(C_ / 64, (B_ * T_) / 64, 1), blk>>>(
        y, Wproj, out, bproj, nullptr, nullptr, 1.0f,
        B_ * T_, C_, C_, C_, C_, C_,
        1, 0, 0, 0, 0, 0, 0, 0, 0, 0, 0);
}

// round 4
// speedup vs baseline: 1.4135x; 1.4135x over previous
#include <cuda_runtime.h>
#include <cuda_bf16.h>
#include <cstdint>

using bf16 = __nv_bfloat16;

static constexpr int B_=4, T_=1024, C_=768, H_=12;
static constexpr long BT=4096, YN=BT*C_, AN=48L*1024*1024;

__device__ __align__(1024) bf16 g_xh[YN], g_xl[YN];
__device__ __align__(1024) bf16 g_wqh[2304L*768], g_wql[2304L*768];
__device__ __align__(1024) bf16 g_wph[768L*768],  g_wpl[768L*768];
__device__ __align__(1024) bf16 g_qh[YN], g_ql[YN], g_kh[YN], g_kl[YN];
__device__ __align__(1024) bf16 g_vh[YN], g_vl[YN], g_vth[YN], g_vtl[YN];
__device__ __align__(1024) float g_logits[AN];
__device__ __align__(1024) bf16 g_ah[AN], g_al[AN];
__device__ __align__(1024) bf16 g_yh[YN], g_yl[YN];

// ---------------- helpers ----------------
__device__ __forceinline__ uint32_t smem_u32(const void* p){
    uint32_t a; asm("{ .reg .u64 t; cvta.to.shared.u64 t, %1; cvt.u32.u64 %0, t; }":"=r"(a):"l"(p)); return a;
}
__device__ __forceinline__ void mma16816(float* c, const uint32_t* a, const uint32_t* b){
    asm volatile("mma.sync.aligned.m16n8k16.row.col.f32.bf16.bf16.f32 "
        "{%0,%1,%2,%3}, {%4,%5,%6,%7}, {%8,%9}, {%0,%1,%2,%3};"
        : "+f"(c[0]),"+f"(c[1]),"+f"(c[2]),"+f"(c[3])
        : "r"(a[0]),"r"(a[1]),"r"(a[2]),"r"(a[3]),"r"(b[0]),"r"(b[1]));
}
__device__ __forceinline__ void ldsm4(uint32_t* r, uint32_t addr){
    asm volatile("ldmatrix.sync.aligned.m8n8.x4.shared.b16 {%0,%1,%2,%3}, [%4];"
        : "=r"(r[0]),"=r"(r[1]),"=r"(r[2]),"=r"(r[3]) : "r"(addr));
}
__device__ __forceinline__ void ldsm2(uint32_t* r, uint32_t addr){
    asm volatile("ldmatrix.sync.aligned.m8n8.x2.shared.b16 {%0,%1}, [%2];"
        : "=r"(r[0]),"=r"(r[1]) : "r"(addr));
}
__device__ __forceinline__ uint32_t pack_bf(float a, float b){
    __nv_bfloat162 t = __floats2bfloat162_rn(a,b);
    return *reinterpret_cast<uint32_t*>(&t);
}
__device__ __forceinline__ void split2(float v, float& h, float& l){
    bf16 hb = __float2bfloat16(v); h = __bfloat162float(hb); l = v - h;
}

// ---------------------------------------------------------------------------
// TN-form bf16 tensor-core GEMM with 3-product hi/lo split.
// A: [M,K] row-major (lda), B: [N,K] row-major (ldb); C = sum A*B^T (fp32).
// Block 128 x TN, 8 warps (2x4), warp 64 x TN/4, K-tile 32.
// MODE 0:qkv  1:logits  2:proj  3:AV
// ---------------------------------------------------------------------------
template<int MODE>
__global__ __launch_bounds__(256)
void gemm_tc(const bf16* __restrict__ Ah, const bf16* __restrict__ Al,
             const bf16* __restrict__ Bh, const bf16* __restrict__ Bl,
             const float* __restrict__ bias1, const float* __restrict__ biasM,
             const float* __restrict__ maskM, float* __restrict__ outF,
             bf16* __restrict__ o1h, bf16* __restrict__ o1l,
             bf16* __restrict__ o2h, bf16* __restrict__ o2l,
             bf16* __restrict__ o3h, bf16* __restrict__ o3l)
{
    constexpr int TN  = (MODE==3)?64:128;
    constexpr int NF  = TN/32;                 // n-frags per warp (8-wide frags): TN/4/8
    constexpr int KT  = (MODE==1)?64:((MODE==3)?1024:768);
    constexpr long LDA = (MODE==3)?1024:768;
    constexpr long LDB = (MODE==3)?1024:768;
    constexpr int NKT = KT/32;

    __shared__ bf16 As[128][40];
    __shared__ bf16 Bs[TN][40];

    const int tid = threadIdx.x, wid = tid>>5, lane = tid&31;
    const int wr = wid>>2, wc = wid&3;               // warp grid 2x4
    const int m_w = wr*64, n_w = wc*(TN/4);
    const int m0 = blockIdx.y*128, n0 = blockIdx.x*TN;
    const int bz = blockIdx.z, bb = bz/H_, hh = bz - bb*H_;

    long aOff, bOff;
    if (MODE==1){ aOff = ((long)bb*1024 + m0)*768 + hh*64; bOff = ((long)bb*1024 + n0)*768 + hh*64; }
    else if (MODE==3){ aOff = (long)bz*1048576 + (long)m0*1024; bOff = (long)bz*65536; }
    else { aOff = (long)m0*LDA; bOff = (long)n0*LDB; }

    const bf16* pAs[3] = {Ah+aOff, Ah+aOff, Al+aOff};
    const bf16* pBs[3] = {Bh+bOff, Bl+bOff, Bh+bOff};

    float acc[4][NF][4];
    #pragma unroll
    for(int i=0;i<4;i++)
        #pragma unroll
        for(int j=0;j<NF;j++)
            #pragma unroll
            for(int k=0;k<4;k++) acc[i][j][k]=0.f;

    // ldmatrix source addresses (fixed per thread)
    const uint32_t aBase = smem_u32(&As[0][0]);
    const uint32_t bBase = smem_u32(&Bs[0][0]);
    const uint32_t aAddr0 = aBase + (uint32_t)(m_w + (lane&15))*80u + (uint32_t)(lane>>4)*16u;
    const uint32_t bAddr0 = bBase + (uint32_t)(n_w + (lane&7))*80u + (uint32_t)((lane>>3)&1)*16u;

    for(int p=0;p<3;++p){
        const bf16* __restrict__ pA = pAs[p];
        const bf16* __restrict__ pB = pBs[p];
        for(int kt=0;kt<NKT;++kt){
            const long k0 = (long)kt*32;
            __syncthreads();
            // load A tile: 512 16B chunks
            #pragma unroll
            for(int i=tid;i<512;i+=256){
                const int r=i>>2, c4=i&3;
                uint4 v = *reinterpret_cast<const uint4*>(pA + (long)r*LDA + k0 + c4*8);
                *reinterpret_cast<uint4*>(&As[r][c4*8]) = v;
            }
            // load B tile
            #pragma unroll
            for(int i=tid;i<TN*4;i+=256){
                const int r=i>>2, c4=i&3;
                uint4 v = *reinterpret_cast<const uint4*>(pB + (long)r*LDB + k0 + c4*8);
                *reinterpret_cast<uint4*>(&Bs[r][c4*8]) = v;
            }
            __syncthreads();
            #pragma unroll
            for(int kf=0;kf<2;++kf){
                uint32_t af[4][4], bfr[NF][2];
                #pragma unroll
                for(int mf=0;mf<4;++mf) ldsm4(af[mf], aAddr0 + (uint32_t)mf*16u*80u + (uint32_t)kf*32u);
                #pragma unroll
                for(int nf=0;nf<NF;++nf) ldsm2(bfr[nf], bAddr0 + (uint32_t)nf*8u*80u + (uint32_t)kf*32u);
                #pragma unroll
                for(int mf=0;mf<4;++mf)
                    #pragma unroll
                    for(int nf=0;nf<NF;++nf)
                        mma16816(acc[mf][nf], af[mf], bfr[nf]);
            }
        }
    }

    // ---------------- epilogue ----------------
    const int qd = lane>>2, rr = lane&3;
    #pragma unroll
    for(int mf=0;mf<4;++mf){
        #pragma unroll
        for(int nf=0;nf<NF;++nf){
            const float* c = acc[mf][nf];
            const int mrow0 = m_w + mf*16 + qd;       // local rows mrow0, mrow0+8
            const int ncol  = n_w + nf*8 + rr*2;      // local col pair
            #pragma unroll
            for(int h2=0;h2<2;++h2){
                const int mloc = mrow0 + h2*8;
                float v0 = c[h2*2+0], v1 = c[h2*2+1];
                if (MODE==1){
                    const long ob = (long)bz*1048576 + (long)(m0+mloc)*1024 + n0 + ncol;
                    const long mb = (long)bb*1048576 + (long)(m0+mloc)*1024 + n0 + ncol;
                    float2 bm = *reinterpret_cast<const float2*>(biasM + ob);
                    float2 mk = *reinterpret_cast<const float2*>(maskM + mb);
                    float2 o; o.x = v0 + bm.x + mk.x; o.y = v1 + bm.y + mk.y;
                    *reinterpret_cast<float2*>(outF + ob) = o;
                } else if (MODE==2){
                    const int ng = n0 + ncol;
                    float2 o; o.x = v0 + bias1[ng]; o.y = v1 + bias1[ng+1];
                    *reinterpret_cast<float2*>(outF + (long)(m0+mloc)*768 + ng) = o;
                } else if (MODE==0){
                    const int ng = n0 + ncol;
                    v0 += bias1[ng]; v1 += bias1[ng+1];
                    bf16 *dh, *dl; int colb; float scl=1.f;
                    if (n0 < 768)      { dh=o1h; dl=o1l; colb = ng;       scl=0.125f; }
                    else if (n0<1536)  { dh=o2h; dl=o2l; colb = ng-768; }
                    else               { dh=o3h; dl=o3l; colb = ng-1536; }
                    v0*=scl; v1*=scl;
                    float h0,l0,h1,l1; split2(v0,h0,l0); split2(v1,h1,l1);
                    const long ob = (long)(m0+mloc)*768 + colb;
                    *reinterpret_cast<uint32_t*>(dh+ob) = pack_bf(h0,h1);
                    *reinterpret_cast<uint32_t*>(dl+ob) = pack_bf(l0,l1);
                } else { // MODE 3: y at [bb*1024+m, hh*64+ncol]
                    float h0,l0,h1,l1; split2(v0,h0,l0); split2(v1,h1,l1);
                    const long ob = ((long)bb*1024 + m0 + mloc)*768 + hh*64 + ncol;
                    *reinterpret_cast<uint32_t*>(o1h+ob) = pack_bf(h0,h1);
                    *reinterpret_cast<uint32_t*>(o1l+ob) = pack_bf(l0,l1);
                }
            }
        }
    }
}

// fp32 -> bf16 hi/lo elementwise split
__global__ __launch_bounds__(256) void splitk(const float4* __restrict__ in,
                                              bf16* __restrict__ oh, bf16* __restrict__ ol, long n4){
    long i = (long)blockIdx.x*256 + threadIdx.x;
    if (i >= n4) return;
    float4 v = in[i];
    float h0,l0,h1,l1,h2,l2,h3,l3;
    split2(v.x,h0,l0); split2(v.y,h1,l1); split2(v.z,h2,l2); split2(v.w,h3,l3);
    *reinterpret_cast<uint2*>(oh + i*4) = make_uint2(pack_bf(h0,h1), pack_bf(h2,h3));
    *reinterpret_cast<uint2*>(ol + i*4) = make_uint2(pack_bf(l0,l1), pack_bf(l2,l3));
}

// W [K,N] fp32 -> Wt [N,K] bf16 hi/lo
__global__ __launch_bounds__(256) void wtsplit(const float* __restrict__ W,
                                               bf16* __restrict__ oh, bf16* __restrict__ ol, int K, int N){
    __shared__ float tf[32][33];
    const int n0 = blockIdx.x*32, k0 = blockIdx.y*32;
    const int tx = threadIdx.x&31, ty = threadIdx.x>>5;
    #pragma unroll
    for(int i=0;i<4;i++) tf[ty+8*i][tx] = W[(long)(k0+ty+8*i)*N + n0+tx];
    __syncthreads();
    #pragma unroll
    for(int i=0;i<4;i++){
        float v = tf[tx][ty+8*i], h,l; split2(v,h,l);
        long o = (long)(n0+ty+8*i)*K + k0+tx;
        oh[o] = __float2bfloat16(h); ol[o] = __float2bfloat16(l);
    }
}

// v [B,T,H*64] -> vt [B*H, 64, 1024]
__global__ __launch_bounds__(256) void vtrans(const bf16* __restrict__ ih, const bf16* __restrict__ il,
                                              bf16* __restrict__ oh, bf16* __restrict__ ol){
    __shared__ bf16 th[32][34], tl[32][34];
    const int t0 = blockIdx.x*32, d0 = blockIdx.y*32, bz = blockIdx.z;
    const int bb = bz/H_, hh = bz - bb*H_;
    const int tx = threadIdx.x&31, ty = threadIdx.x>>5;
    const long ib = ((long)bb*1024 + t0)*768 + hh*64 + d0;
    #pragma unroll
    for(int i=0;i<4;i++){
        th[ty+8*i][tx] = ih[ib + (long)(ty+8*i)*768 + tx];
        tl[ty+8*i][tx] = il[ib + (long)(ty+8*i)*768 + tx];
    }
    __syncthreads();
    const long ob = ((long)bz*64 + d0)*1024 + t0;
    #pragma unroll
    for(int i=0;i<4;i++){
        oh[ob + (long)(ty+8*i)*1024 + tx] = th[tx][ty+8*i];
        ol[ob + (long)(ty+8*i)*1024 + tx] = tl[tx][ty+8*i];
    }
}

// softmax over 1024-wide rows; writes fp32 attn + bf16 hi/lo attn
__global__ __launch_bounds__(256) void softmax_kernel(const float* __restrict__ in, float* __restrict__ out,
                                                      bf16* __restrict__ oh, bf16* __restrict__ ol){
    const long row = blockIdx.x;
    const float4* ip = (const float4*)(in + row*1024);
    const int tid = threadIdx.x;
    __shared__ float sred[8];
    float4 v = ip[tid];
    float m = fmaxf(fmaxf(v.x,v.y), fmaxf(v.z,v.w));
    #pragma unroll
    for(int o=16;o;o>>=1) m = fmaxf(m, __shfl_xor_sync(0xffffffffu,m,o));
    if((tid&31)==0) sred[tid>>5]=m;
    __syncthreads();
    float gm = sred[0];
    #pragma unroll
    for(int i=1;i<8;i++) gm = fmaxf(gm, sred[i]);
    __syncthreads();
    v.x=__expf(v.x-gm); v.y=__expf(v.y-gm); v.z=__expf(v.z-gm); v.w=__expf(v.w-gm);
    float s = v.x+v.y+v.z+v.w;
    #pragma unroll
    for(int o=16;o;o>>=1) s += __shfl_xor_sync(0xffffffffu,s,o);
    if((tid&31)==0) sred[tid>>5]=s;
    __syncthreads();
    float gs = sred[0];
    #pragma unroll
    for(int i=1;i<8;i++) gs += sred[i];
    const float inv = 1.0f/gs;
    v.x*=inv; v.y*=inv; v.z*=inv; v.w*=inv;
    *(float4*)(out + row*1024 + tid*4) = v;
    float h0,l0,h1,l1,h2,l2,h3,l3;
    split2(v.x,h0,l0); split2(v.y,h1,l1); split2(v.z,h2,l2); split2(v.w,h3,l3);
    *reinterpret_cast<uint2*>(oh + row*1024 + tid*4) = make_uint2(pack_bf(h0,h1), pack_bf(h2,h3));
    *reinterpret_cast<uint2*>(ol + row*1024 + tid*4) = make_uint2(pack_bf(l0,l1), pack_bf(l2,l3));
}

extern "C" void kernel_launch(void* const* d_in, const int* in_sizes, int n_in,
                              void* d_out, int out_size)
{
    const float* x     = (const float*)d_in[0];
    const float* mask  = (const float*)d_in[1];
    const float* bias  = (const float*)d_in[2];
    const float* Wqkv  = (const float*)d_in[3];
    const float* bqkv  = (const float*)d_in[4];
    const float* Wproj = (const float*)d_in[5];
    const float* bproj = (const float*)d_in[6];
    float* out = (float*)d_out;

    bf16 *xh,*xl,*wqh,*wql,*wph,*wpl,*qh,*ql,*kh,*kl,*vh,*vl,*vth,*vtl,*ah,*al,*yh,*yl;
    float *logits;
    cudaGetSymbolAddress((void**)&xh,g_xh);   cudaGetSymbolAddress((void**)&xl,g_xl);
    cudaGetSymbolAddress((void**)&wqh,g_wqh); cudaGetSymbolAddress((void**)&wql,g_wql);
    cudaGetSymbolAddress((void**)&wph,g_wph); cudaGetSymbolAddress((void**)&wpl,g_wpl);
    cudaGetSymbolAddress((void**)&qh,g_qh);   cudaGetSymbolAddress((void**)&ql,g_ql);
    cudaGetSymbolAddress((void**)&kh,g_kh);   cudaGetSymbolAddress((void**)&kl,g_kl);
    cudaGetSymbolAddress((void**)&vh,g_vh);   cudaGetSymbolAddress((void**)&vl,g_vl);
    cudaGetSymbolAddress((void**)&vth,g_vth); cudaGetSymbolAddress((void**)&vtl,g_vtl);
    cudaGetSymbolAddress((void**)&ah,g_ah);   cudaGetSymbolAddress((void**)&al,g_al);
    cudaGetSymbolAddress((void**)&yh,g_yh);   cudaGetSymbolAddress((void**)&yl,g_yl);
    cudaGetSymbolAddress((void**)&logits,g_logits);

    float* attn = ((long)out_size >= YN + AN) ? (out + YN) : logits;

    // 1) split x into bf16 hi/lo
    splitk<<<(YN/4+255)/256, 256>>>((const float4*)x, xh, xl, YN/4);
    // 2) transpose-split weights to [N,K] hi/lo
    wtsplit<<<dim3(2304/32, 768/32), 256>>>(Wqkv, wqh, wql, 768, 2304);
    wtsplit<<<dim3(768/32, 768/32),  256>>>(Wproj, wph, wpl, 768, 768);
    // 3) qkv GEMM -> q(scaled)/k/v hi+lo
    gemm_tc<0><<<dim3(18,32,1), 256>>>(xh, xl, wqh, wql, bqkv, nullptr, nullptr, nullptr,
                                       qh, ql, kh, kl, vh, vl);
    // 4) transpose v -> [B*H,64,1024]
    vtrans<<<dim3(32,2,48), 256>>>(vh, vl, vth, vtl);
    // 5) logits = q k^T + bias + mask
    gemm_tc<1><<<dim3(8,8,48), 256>>>(qh, ql, kh, kl, nullptr, bias, mask, logits,
                                      nullptr,nullptr,nullptr,nullptr,nullptr,nullptr);
    // 6) softmax -> attn fp32 (possibly straight into d_out) + bf16 hi/lo
    softmax_kernel<<<48*1024, 256>>>(logits, attn, ah, al);
    // 7) y = attn @ v^T
    gemm_tc<3><<<dim3(1,8,48), 256>>>(ah, al, vth, vtl, nullptr, nullptr, nullptr, nullptr,
                                      yh, yl, nullptr,nullptr,nullptr,nullptr);
    // 8) out = y @ Wproj + bproj
    gemm_tc<2><<<dim3(6,32,1), 256>>>(yh, yl, wph, wpl, bproj, nullptr, nullptr, out,
                                      nullptr,nullptr,nullptr,nullptr,nullptr,nullptr);
}

// round 5
// speedup vs baseline: 1.9699x; 1.3936x over previous
#include <cuda_runtime.h>
#include <cuda_bf16.h>
#include <cstdint>

using bf16 = __nv_bfloat16;

static constexpr int B_=4, T_=1024, C_=768, H_=12;
static constexpr long BT=4096, YN=BT*C_, AN=48L*1024*1024;

__device__ __align__(1024) bf16 g_xh[YN], g_xl[YN];
__device__ __align__(1024) bf16 g_wqh[2304L*768], g_wql[2304L*768];
__device__ __align__(1024) bf16 g_wph[768L*768],  g_wpl[768L*768];
__device__ __align__(1024) bf16 g_qh[YN], g_ql[YN], g_kh[YN], g_kl[YN];
__device__ __align__(1024) bf16 g_vh[YN], g_vl[YN], g_vth[YN], g_vtl[YN];
__device__ __align__(1024) float g_logits[AN];
__device__ __align__(1024) bf16 g_ah[AN], g_al[AN];
__device__ __align__(1024) bf16 g_yh[YN], g_yl[YN];

// ---------------- helpers ----------------
__device__ __forceinline__ uint32_t smem_u32(const void* p){
    uint32_t a; asm("{ .reg .u64 t; cvta.to.shared.u64 t, %1; cvt.u32.u64 %0, t; }":"=r"(a):"l"(p)); return a;
}
__device__ __forceinline__ void mma16816(float* c, const uint32_t* a, const uint32_t* b){
    asm volatile("mma.sync.aligned.m16n8k16.row.col.f32.bf16.bf16.f32 "
        "{%0,%1,%2,%3}, {%4,%5,%6,%7}, {%8,%9}, {%0,%1,%2,%3};"
        : "+f"(c[0]),"+f"(c[1]),"+f"(c[2]),"+f"(c[3])
        : "r"(a[0]),"r"(a[1]),"r"(a[2]),"r"(a[3]),"r"(b[0]),"r"(b[1]));
}
__device__ __forceinline__ void ldsm4(uint32_t* r, uint32_t addr){
    asm volatile("ldmatrix.sync.aligned.m8n8.x4.shared.b16 {%0,%1,%2,%3}, [%4];"
        : "=r"(r[0]),"=r"(r[1]),"=r"(r[2]),"=r"(r[3]) : "r"(addr));
}
__device__ __forceinline__ void ldsm2(uint32_t* r, uint32_t addr){
    asm volatile("ldmatrix.sync.aligned.m8n8.x2.shared.b16 {%0,%1}, [%2];"
        : "=r"(r[0]),"=r"(r[1]) : "r"(addr));
}
__device__ __forceinline__ void cpasync16(uint32_t dst, const void* src){
    asm volatile("cp.async.cg.shared.global [%0], [%1], 16;" :: "r"(dst), "l"(src));
}
__device__ __forceinline__ void cpcommit(){ asm volatile("cp.async.commit_group;" ::: "memory"); }
template<int N> __device__ __forceinline__ void cpwait(){ asm volatile("cp.async.wait_group %0;" :: "n"(N) : "memory"); }
__device__ __forceinline__ uint32_t pack_bf(float a, float b){
    __nv_bfloat162 t = __floats2bfloat162_rn(a,b);
    return *reinterpret_cast<uint32_t*>(&t);
}
__device__ __forceinline__ void split2(float v, float& h, float& l){
    bf16 hb = __float2bfloat16(v); h = __bfloat162float(hb); l = v - h;
}

// ---------------------------------------------------------------------------
// TN-form bf16 tensor-core GEMM, 3-product hi/lo split, fused tile loads,
// cp.async double-buffered. A:[M,K] (lda), B:[N,K] (ldb); C = A*B^T fp32.
// Block 128 x TN, 8 warps (2x4), K-step 32.
// MODE 0:qkv  1:logits  2:proj  3:AV
// ---------------------------------------------------------------------------
template<int MODE>
__global__ __launch_bounds__(256)
void gemm_tc(const bf16* __restrict__ Ah, const bf16* __restrict__ Al,
             const bf16* __restrict__ Bh, const bf16* __restrict__ Bl,
             const float* __restrict__ bias1, const float* __restrict__ biasM,
             const float* __restrict__ maskM, float* __restrict__ outF,
             bf16* __restrict__ o1h, bf16* __restrict__ o1l,
             bf16* __restrict__ o2h, bf16* __restrict__ o2l,
             bf16* __restrict__ o3h, bf16* __restrict__ o3l)
{
    constexpr int TN  = (MODE==3)?64:128;
    constexpr int NF  = TN/32;
    constexpr int KT  = (MODE==1)?64:((MODE==3)?1024:768);
    constexpr long LDA = (MODE==3)?1024:768;
    constexpr long LDB = (MODE==3)?1024:768;
    constexpr int NKT = KT/32;
    constexpr uint32_t TSA  = 10240u;        // bytes per 128x32 A tile (pitch 80B)
    constexpr uint32_t TSB  = TN*80u;        // bytes per TNx32 B tile
    constexpr uint32_t BUFB = 2u*TSA + 2u*TSB;

    extern __shared__ bf16 smem[];
    const uint32_t sb0 = smem_u32(smem);

    const int tid = threadIdx.x, wid = tid>>5, lane = tid&31;
    const int wr = wid>>2, wc = wid&3;
    const int m_w = wr*64, n_w = wc*(TN/4);
    const int m0 = blockIdx.y*128, n0 = blockIdx.x*TN;
    const int bz = blockIdx.z, bb = bz/H_, hh = bz - bb*H_;

    long aOff, bOff;
    if (MODE==1){ aOff = ((long)bb*1024 + m0)*768 + hh*64; bOff = ((long)bb*1024 + n0)*768 + hh*64; }
    else if (MODE==3){ aOff = (long)bz*1048576 + (long)m0*1024; bOff = (long)bz*65536; }
    else { aOff = (long)m0*LDA; bOff = (long)n0*LDB; }
    const bf16 *pAh=Ah+aOff, *pAl=Al+aOff, *pBh=Bh+bOff, *pBl=Bl+bOff;

    float acc[4][NF][4];
    #pragma unroll
    for(int i=0;i<4;i++)
        #pragma unroll
        for(int j=0;j<NF;j++)
            #pragma unroll
            for(int k=0;k<4;k++) acc[i][j][k]=0.f;

    const uint32_t aAddrB = sb0 + (uint32_t)(m_w + (lane&15))*80u + (uint32_t)(lane>>4)*16u;
    const uint32_t bAddrB = sb0 + (uint32_t)(n_w + (lane&7))*80u + (uint32_t)((lane>>3)&1)*16u;

    auto issue = [&](int kt, int buf){
        const long k0 = (long)kt*32;
        const uint32_t base = sb0 + (uint32_t)buf*BUFB;
        #pragma unroll
        for(int it=0; it<4; ++it){                 // A hi+lo: 1024 x 16B
            const int i = tid + it*256;
            const int t = i>>9, j = i&511, r = j>>2, c = j&3;
            const bf16* src = (t? pAl : pAh) + (long)r*LDA + k0 + c*8;
            cpasync16(base + (uint32_t)t*TSA + (uint32_t)(r*80 + c*16), src);
        }
        #pragma unroll
        for(int it=0; it<TN/32; ++it){             // B hi+lo: TN*8 x 16B
            const int i = tid + it*256;
            const int t = (i >= TN*4);
            const int j = t ? i - TN*4 : i;
            const int r = j>>2, c = j&3;
            const bf16* src = (t? pBl : pBh) + (long)r*LDB + k0 + c*8;
            cpasync16(base + 2u*TSA + (uint32_t)t*TSB + (uint32_t)(r*80 + c*16), src);
        }
        cpcommit();
    };

    issue(0, 0);
    for(int kt=0; kt<NKT; ++kt){
        const int cb = kt&1;
        if (kt+1 < NKT){ issue(kt+1, cb^1); cpwait<1>(); }
        else           { cpwait<0>(); }
        __syncthreads();

        const uint32_t aH = aAddrB + (uint32_t)cb*BUFB;
        const uint32_t aL = aH + TSA;
        const uint32_t bH = bAddrB + (uint32_t)cb*BUFB + 2u*TSA;
        const uint32_t bL = bH + TSB;
        #pragma unroll
        for(int kf=0; kf<2; ++kf){
            uint32_t a4[4][4], b2h[NF][2], b2l[NF][2];
            #pragma unroll
            for(int mf=0; mf<4; ++mf) ldsm4(a4[mf], aH + (uint32_t)mf*1280u + (uint32_t)kf*32u);
            #pragma unroll
            for(int nf=0; nf<NF; ++nf){
                ldsm2(b2h[nf], bH + (uint32_t)nf*640u + (uint32_t)kf*32u);
                ldsm2(b2l[nf], bL + (uint32_t)nf*640u + (uint32_t)kf*32u);
            }
            #pragma unroll
            for(int mf=0; mf<4; ++mf)
                #pragma unroll
                for(int nf=0; nf<NF; ++nf) mma16816(acc[mf][nf], a4[mf], b2h[nf]);
            #pragma unroll
            for(int mf=0; mf<4; ++mf)
                #pragma unroll
                for(int nf=0; nf<NF; ++nf) mma16816(acc[mf][nf], a4[mf], b2l[nf]);
            #pragma unroll
            for(int mf=0; mf<4; ++mf) ldsm4(a4[mf], aL + (uint32_t)mf*1280u + (uint32_t)kf*32u);
            #pragma unroll
            for(int mf=0; mf<4; ++mf)
                #pragma unroll
                for(int nf=0; nf<NF; ++nf) mma16816(acc[mf][nf], a4[mf], b2h[nf]);
        }
        __syncthreads();
    }

    // ---------------- epilogue ----------------
    const int qd = lane>>2, rr = lane&3;
    #pragma unroll
    for(int mf=0;mf<4;++mf){
        #pragma unroll
        for(int nf=0;nf<NF;++nf){
            const float* c = acc[mf][nf];
            const int mrow0 = m_w + mf*16 + qd;
            const int ncol  = n_w + nf*8 + rr*2;
            #pragma unroll
            for(int h2=0;h2<2;++h2){
                const int mloc = mrow0 + h2*8;
                float v0 = c[h2*2+0], v1 = c[h2*2+1];
                if (MODE==1){
                    const long ob = (long)bz*1048576 + (long)(m0+mloc)*1024 + n0 + ncol;
                    const long mb = (long)bb*1048576 + (long)(m0+mloc)*1024 + n0 + ncol;
                    float2 bm = *reinterpret_cast<const float2*>(biasM + ob);
                    float2 mk = *reinterpret_cast<const float2*>(maskM + mb);
                    float2 o; o.x = v0 + bm.x + mk.x; o.y = v1 + bm.y + mk.y;
                    *reinterpret_cast<float2*>(outF + ob) = o;
                } else if (MODE==2){
                    const int ng = n0 + ncol;
                    float2 o; o.x = v0 + bias1[ng]; o.y = v1 + bias1[ng+1];
                    *reinterpret_cast<float2*>(outF + (long)(m0+mloc)*768 + ng) = o;
                } else if (MODE==0){
                    const int ng = n0 + ncol;
                    v0 += bias1[ng]; v1 += bias1[ng+1];
                    bf16 *dh, *dl; int colb; float scl=1.f;
                    if (n0 < 768)      { dh=o1h; dl=o1l; colb = ng;       scl=0.125f; }
                    else if (n0<1536)  { dh=o2h; dl=o2l; colb = ng-768; }
                    else               { dh=o3h; dl=o3l; colb = ng-1536; }
                    v0*=scl; v1*=scl;
                    float h0,l0,h1,l1; split2(v0,h0,l0); split2(v1,h1,l1);
                    const long ob = (long)(m0+mloc)*768 + colb;
                    *reinterpret_cast<uint32_t*>(dh+ob) = pack_bf(h0,h1);
                    *reinterpret_cast<uint32_t*>(dl+ob) = pack_bf(l0,l1);
                } else {
                    float h0,l0,h1,l1; split2(v0,h0,l0); split2(v1,h1,l1);
                    const long ob = ((long)bb*1024 + m0 + mloc)*768 + hh*64 + ncol;
                    *reinterpret_cast<uint32_t*>(o1h+ob) = pack_bf(h0,h1);
                    *reinterpret_cast<uint32_t*>(o1l+ob) = pack_bf(l0,l1);
                }
            }
        }
    }
}

// fp32 -> bf16 hi/lo elementwise split
__global__ __launch_bounds__(256) void splitk(const float4* __restrict__ in,
                                              bf16* __restrict__ oh, bf16* __restrict__ ol, long n4){
    long i = (long)blockIdx.x*256 + threadIdx.x;
    if (i >= n4) return;
    float4 v = in[i];
    float h0,l0,h1,l1,h2,l2,h3,l3;
    split2(v.x,h0,l0); split2(v.y,h1,l1); split2(v.z,h2,l2); split2(v.w,h3,l3);
    *reinterpret_cast<uint2*>(oh + i*4) = make_uint2(pack_bf(h0,h1), pack_bf(h2,h3));
    *reinterpret_cast<uint2*>(ol + i*4) = make_uint2(pack_bf(l0,l1), pack_bf(l2,l3));
}

// W [K,N] fp32 -> Wt [N,K] bf16 hi/lo
__global__ __launch_bounds__(256) void wtsplit(const float* __restrict__ W,
                                               bf16* __restrict__ oh, bf16* __restrict__ ol, int K, int N){
    __shared__ float tf[32][33];
    const int n0 = blockIdx.x*32, k0 = blockIdx.y*32;
    const int tx = threadIdx.x&31, ty = threadIdx.x>>5;
    #pragma unroll
    for(int i=0;i<4;i++) tf[ty+8*i][tx] = W[(long)(k0+ty+8*i)*N + n0+tx];
    __syncthreads();
    #pragma unroll
    for(int i=0;i<4;i++){
        float v = tf[tx][ty+8*i], h,l; split2(v,h,l);
        long o = (long)(n0+ty+8*i)*K + k0+tx;
        oh[o] = __float2bfloat16(h); ol[o] = __float2bfloat16(l);
    }
}

// v [B,T,H*64] -> vt [B*H, 64, 1024]
__global__ __launch_bounds__(256) void vtrans(const bf16* __restrict__ ih, const bf16* __restrict__ il,
                                              bf16* __restrict__ oh, bf16* __restrict__ ol){
    __shared__ bf16 th[32][34], tl[32][34];
    const int t0 = blockIdx.x*32, d0 = blockIdx.y*32, bz = blockIdx.z;
    const int bb = bz/H_, hh = bz - bb*H_;
    const int tx = threadIdx.x&31, ty = threadIdx.x>>5;
    const long ib = ((long)bb*1024 + t0)*768 + hh*64 + d0;
    #pragma unroll
    for(int i=0;i<4;i++){
        th[ty+8*i][tx] = ih[ib + (long)(ty+8*i)*768 + tx];
        tl[ty+8*i][tx] = il[ib + (long)(ty+8*i)*768 + tx];
    }
    __syncthreads();
    const long ob = ((long)bz*64 + d0)*1024 + t0;
    #pragma unroll
    for(int i=0;i<4;i++){
        oh[ob + (long)(ty+8*i)*1024 + tx] = th[tx][ty+8*i];
        ol[ob + (long)(ty+8*i)*1024 + tx] = tl[tx][ty+8*i];
    }
}

// softmax over 1024-wide rows; writes fp32 attn + bf16 hi/lo attn
__global__ __launch_bounds__(256) void softmax_kernel(const float* __restrict__ in, float* __restrict__ out,
                                                      bf16* __restrict__ oh, bf16* __restrict__ ol){
    const long row = blockIdx.x;
    const float4* ip = (const float4*)(in + row*1024);
    const int tid = threadIdx.x;
    __shared__ float sred[8];
    float4 v = ip[tid];
    float m = fmaxf(fmaxf(v.x,v.y), fmaxf(v.z,v.w));
    #pragma unroll
    for(int o=16;o;o>>=1) m = fmaxf(m, __shfl_xor_sync(0xffffffffu,m,o));
    if((tid&31)==0) sred[tid>>5]=m;
    __syncthreads();
    float gm = sred[0];
    #pragma unroll
    for(int i=1;i<8;i++) gm = fmaxf(gm, sred[i]);
    __syncthreads();
    v.x=__expf(v.x-gm); v.y=__expf(v.y-gm); v.z=__expf(v.z-gm); v.w=__expf(v.w-gm);
    float s = v.x+v.y+v.z+v.w;
    #pragma unroll
    for(int o=16;o;o>>=1) s += __shfl_xor_sync(0xffffffffu,s,o);
    if((tid&31)==0) sred[tid>>5]=s;
    __syncthreads();
    float gs = sred[0];
    #pragma unroll
    for(int i=1;i<8;i++) gs += sred[i];
    const float inv = 1.0f/gs;
    v.x*=inv; v.y*=inv; v.z*=inv; v.w*=inv;
    *(float4*)(out + row*1024 + tid*4) = v;
    float h0,l0,h1,l1,h2,l2,h3,l3;
    split2(v.x,h0,l0); split2(v.y,h1,l1); split2(v.z,h2,l2); split2(v.w,h3,l3);
    *reinterpret_cast<uint2*>(oh + row*1024 + tid*4) = make_uint2(pack_bf(h0,h1), pack_bf(h2,h3));
    *reinterpret_cast<uint2*>(ol + row*1024 + tid*4) = make_uint2(pack_bf(l0,l1), pack_bf(l2,l3));
}

extern "C" void kernel_launch(void* const* d_in, const int* in_sizes, int n_in,
                              void* d_out, int out_size)
{
    const float* x     = (const float*)d_in[0];
    const float* mask  = (const float*)d_in[1];
    const float* bias  = (const float*)d_in[2];
    const float* Wqkv  = (const float*)d_in[3];
    const float* bqkv  = (const float*)d_in[4];
    const float* Wproj = (const float*)d_in[5];
    const float* bproj = (const float*)d_in[6];
    float* out = (float*)d_out;

    bf16 *xh,*xl,*wqh,*wql,*wph,*wpl,*qh,*ql,*kh,*kl,*vh,*vl,*vth,*vtl,*ah,*al,*yh,*yl;
    float *logits;
    cudaGetSymbolAddress((void**)&xh,g_xh);   cudaGetSymbolAddress((void**)&xl,g_xl);
    cudaGetSymbolAddress((void**)&wqh,g_wqh); cudaGetSymbolAddress((void**)&wql,g_wql);
    cudaGetSymbolAddress((void**)&wph,g_wph); cudaGetSymbolAddress((void**)&wpl,g_wpl);
    cudaGetSymbolAddress((void**)&qh,g_qh);   cudaGetSymbolAddress((void**)&ql,g_ql);
    cudaGetSymbolAddress((void**)&kh,g_kh);   cudaGetSymbolAddress((void**)&kl,g_kl);
    cudaGetSymbolAddress((void**)&vh,g_vh);   cudaGetSymbolAddress((void**)&vl,g_vl);
    cudaGetSymbolAddress((void**)&vth,g_vth); cudaGetSymbolAddress((void**)&vtl,g_vtl);
    cudaGetSymbolAddress((void**)&ah,g_ah);   cudaGetSymbolAddress((void**)&al,g_al);
    cudaGetSymbolAddress((void**)&yh,g_yh);   cudaGetSymbolAddress((void**)&yl,g_yl);
    cudaGetSymbolAddress((void**)&logits,g_logits);

    float* attn = ((long)out_size >= YN + AN) ? (out + YN) : logits;

    const int smemBig = 81920;   // MODE 0/1/2: 2*(2*10240 + 2*10240)
    const int smemAV  = 61440;   // MODE 3:     2*(2*10240 + 2*5120)
    cudaFuncSetAttribute(gemm_tc<0>, cudaFuncAttributeMaxDynamicSharedMemorySize, smemBig);
    cudaFuncSetAttribute(gemm_tc<1>, cudaFuncAttributeMaxDynamicSharedMemorySize, smemBig);
    cudaFuncSetAttribute(gemm_tc<2>, cudaFuncAttributeMaxDynamicSharedMemorySize, smemBig);
    cudaFuncSetAttribute(gemm_tc<3>, cudaFuncAttributeMaxDynamicSharedMemorySize, smemAV);

    // 1) split x into bf16 hi/lo
    splitk<<<(YN/4+255)/256, 256>>>((const float4*)x, xh, xl, YN/4);
    // 2) transpose-split weights to [N,K] hi/lo
    wtsplit<<<dim3(2304/32, 768/32), 256>>>(Wqkv, wqh, wql, 768, 2304);
    wtsplit<<<dim3(768/32, 768/32),  256>>>(Wproj, wph, wpl, 768, 768);
    // 3) qkv GEMM -> q(scaled)/k/v hi+lo
    gemm_tc<0><<<dim3(18,32,1), 256, smemBig>>>(xh, xl, wqh, wql, bqkv, nullptr, nullptr, nullptr,
                                                qh, ql, kh, kl, vh, vl);
    // 4) transpose v -> [B*H,64,1024]
    vtrans<<<dim3(32,2,48), 256>>>(vh, vl, vth, vtl);
    // 5) logits = q k^T + bias + mask
    gemm_tc<1><<<dim3(8,8,48), 256, smemBig>>>(qh, ql, kh, kl, nullptr, bias, mask, logits,
                                               nullptr,nullptr,nullptr,nullptr,nullptr,nullptr);
    // 6) softmax -> attn fp32 (possibly straight into d_out) + bf16 hi/lo
    softmax_kernel<<<48*1024, 256>>>(logits, attn, ah, al);
    // 7) y = attn @ v^T
    gemm_tc<3><<<dim3(1,8,48), 256, smemAV>>>(ah, al, vth, vtl, nullptr, nullptr, nullptr, nullptr,
                                              yh, yl, nullptr,nullptr,nullptr,nullptr);
    // 8) out = y @ Wproj + bproj
    gemm_tc<2><<<dim3(6,32,1), 256, smemBig>>>(yh, yl, wph, wpl, bproj, nullptr, nullptr, out,
                                               nullptr,nullptr,nullptr,nullptr,nullptr,nullptr);
}